// round 17
// baseline (speedup 1.0000x reference)
#include <cuda_runtime.h>
#include <math.h>

// ---------------- static problem constants ----------------
#define BGR 4
#define NN  40962
#define DEG 6
#define E0C (BGR * NN * DEG)          // 983052
#define M0  (BGR * NN)                // 163848

static const int NIN[4] = {40962, 20481, 10241, 5121};   // nodes/graph entering layer i
static const int KK [4] = {20481, 10241,  5121, 2561};   // kept/graph after pool i

// ---------------- device scratch (static, no allocation) ----------------
__device__ __align__(128) float    g_H  [5243392];
__device__ __align__(128) float    g_XB [5243392];
__device__ __align__(128) float    g_XA [2621952];
__device__ float    g_deg[M0];
__device__ float    g_dinv[M0];
__device__ float    g_score[M0];
__device__ unsigned g_key[M0];
__device__ int      g_remap[M0];
__device__ int      g_srcbuf[2 * E0C];
__device__ int      g_dstbuf[2 * E0C];
__device__ int      g_ecnt[2];
__device__ int      g_E0 = E0C;        // static full-edge count for layer 0
__device__ unsigned g_hist12[BGR * 4096];
__device__ unsigned g_thresh[BGR];
__device__ int      g_allow[BGR];
__device__ int      g_cntK[BGR];
__device__ int      g_cntE[BGR];
__device__ float    g_pinv[4];
__device__ float    g_pmax[32 * 128];
__device__ float    g_psum[32 * 128];
__device__ unsigned g_misc[8];         // [0..3] scoresel tickets, [4] readout ticket

// ---------------- helpers ----------------
__device__ __forceinline__ unsigned long long pack2(float a, float b) {
    unsigned long long r;
    asm("mov.b64 %0,{%1,%2};" : "=l"(r) : "f"(a), "f"(b));
    return r;
}
__device__ __forceinline__ void unpack2(unsigned long long v, float& a, float& b) {
    asm("mov.b64 {%0,%1},%2;" : "=f"(a), "=f"(b) : "l"(v));
}
__device__ __forceinline__ void ffma2(unsigned long long& acc, unsigned long long x,
                                      unsigned long long w) {
    asm("fma.rn.f32x2 %0,%1,%2,%0;" : "+l"(acc) : "l"(x), "l"(w));
}
__device__ __forceinline__ void red4(float* p, float4 v) {
    asm volatile("red.global.add.v4.f32 [%0],{%1,%2,%3,%4};"
                 :: "l"(p), "f"(v.x), "f"(v.y), "f"(v.z), "f"(v.w) : "memory");
}
__device__ __forceinline__ void gdep() { cudaGridDependencySynchronize(); }

// ---------------- kernels ----------------
// init: layer-0 degree count (deg pre-zeroed by memset) + pinv[4]
__global__ void k_init(const int* __restrict__ dst,
                       const float* __restrict__ p1, const float* __restrict__ p2,
                       const float* __restrict__ p3, const float* __restrict__ p4,
                       float* __restrict__ deg, float* __restrict__ pinv) {
    gdep();
    int e = blockIdx.x * blockDim.x + threadIdx.x;
    if (e < E0C) atomicAdd(&deg[dst[e]], 1.0f);
    if (blockIdx.x < 4 && threadIdx.x < 32) {
        const float* p = (blockIdx.x == 0) ? p1 : (blockIdx.x == 1) ? p2
                         : (blockIdx.x == 2) ? p3 : p4;
        int len = (blockIdx.x == 0) ? 32 : (blockIdx.x == 1) ? 64 : 128;
        float acc = 0.f;
        for (int f = threadIdx.x; f < len; f += 32) { float v = p[f]; acc += v * v; }
#pragma unroll
        for (int o = 16; o; o >>= 1) acc += __shfl_down_sync(0xffffffffu, acc, o);
        if (threadIdx.x == 0) pinv[blockIdx.x] = rsqrtf(acc);
    }
}

// smem-tiled matmul: H = XB = (X@W) * dinv[m]
template <int FI, int FO>
__global__ void k_mm(const float* __restrict__ X, const float* __restrict__ W,
                     const float* __restrict__ deg, float* __restrict__ H,
                     float* __restrict__ XB, int M) {
    gdep();
    constexpr int J = FO / 4;
    constexpr int G = 256 / J;
    __shared__ float sX[G * FI];
    int r0 = blockIdx.x * G;
    for (int idx = threadIdx.x; idx < G * FI; idx += 256) {
        int r = r0 + idx / FI;
        sX[idx] = (r < M) ? X[(size_t)r * FI + (idx % FI)] : 0.f;
    }
    __syncthreads();
    int g = threadIdx.x / J, j = (threadIdx.x % J) * 4;
    int m = r0 + g;
    if (m >= M) return;
    const float* xr = sX + g * FI;
    unsigned long long acc0 = 0ull, acc1 = 0ull;
#pragma unroll
    for (int kq = 0; kq < FI; kq++) {
        float xv = xr[kq];
        unsigned long long xx = pack2(xv, xv);
        ulonglong2 wv = *(const ulonglong2*)(W + kq * FO + j);
        ffma2(acc0, xx, wv.x);
        ffma2(acc1, xx, wv.y);
    }
    float a0, a1, a2, a3;
    unpack2(acc0, a0, a1);
    unpack2(acc1, a2, a3);
    float dv = rsqrtf(deg[m] + 1.0f);
    float4 hv = make_float4(a0 * dv, a1 * dv, a2 * dv, a3 * dv);
    *(float4*)(H + (size_t)m * FO + j) = hv;
    *(float4*)(XB + (size_t)m * FO + j) = hv;
}

// edge aggregation: XB[d] += H'[s], thread per (edge, 4-feature chunk), v4 RED
template <int FO>
__global__ void k_agg(const int* __restrict__ src, const int* __restrict__ dst,
                      const int* __restrict__ ecnt, const float* __restrict__ H,
                      float* __restrict__ XB) {
    gdep();
    constexpr int LC = (FO == 32) ? 3 : (FO == 64) ? 4 : 5;
    constexpr int CM = (1 << LC) - 1;
    int total = (*ecnt) << LC;
    int t = blockIdx.x * blockDim.x + threadIdx.x;
    int stride = gridDim.x * blockDim.x;
    for (int i = t; i < total; i += stride) {
        int e = i >> LC, c = i & CM;
        int s = src[e], d = dst[e];
        float4 h = *(const float4*)(H + (size_t)s * FO + c * 4);
        red4(XB + (size_t)d * FO + c * 4, h);
    }
}

// fused score + (last-block-per-graph) radix select.
// Blocks graph-partitioned: 1024 threads = 32 warp-per-node rows. Also stores
// dinv[m] so cg never touches deg (removes all deg ordering hazards).
template <int FO>
__global__ void __launch_bounds__(1024)
k_scoresel(const float* __restrict__ XB, const float* __restrict__ deg,
           const float* __restrict__ bias, const float* __restrict__ p,
           int n, int bpg, int k,
           float* __restrict__ score, unsigned* __restrict__ key,
           float* __restrict__ dinv,
           unsigned* __restrict__ hist12, unsigned* __restrict__ thresh,
           int* __restrict__ allow, int* __restrict__ cntK, int* __restrict__ cntE,
           int* __restrict__ eCn, unsigned* __restrict__ scnt) {
    gdep();
    __shared__ unsigned sh[4096];
    __shared__ unsigned arr[1024];
    __shared__ unsigned sPfx;
    __shared__ int sW;
    __shared__ unsigned sTicket;

    int g = blockIdx.x / bpg, bi = blockIdx.x % bpg;
    int wid = threadIdx.x >> 5, lane = threadIdx.x & 31;
    int local = bi * 32 + wid;

    // ---- score phase ----
    if (local < n) {
        int m = g * n + local;
        float dv = rsqrtf(deg[m] + 1.0f);
        float acc = 0.f;
#pragma unroll
        for (int f = lane; f < FO; f += 32) {
            float v = XB[(size_t)m * FO + f] * dv + bias[f];
            acc += fmaxf(v, 0.f) * p[f];
        }
#pragma unroll
        for (int o = 16; o; o >>= 1) acc += __shfl_down_sync(0xffffffffu, acc, o);
        if (lane == 0) {
            score[m] = acc;
            dinv[m] = dv;
            unsigned u = __float_as_uint(acc);
            unsigned kk = (u & 0x80000000u) ? ~u : (u | 0x80000000u);
            key[m] = kk;
            atomicAdd(&hist12[g * 4096 + (kk >> 20)], 1u);
        }
    }

    // ---- election: last block of this graph runs select ----
    __threadfence();
    __syncthreads();
    if (threadIdx.x == 0) sTicket = atomicAdd(&scnt[g], 1u);
    __syncthreads();
    if (sTicket != (unsigned)(bpg - 1)) return;
    __threadfence();

    int t = threadIdx.x;
    const unsigned* kb = key + g * n;
    unsigned* hb = hist12 + g * 4096;

    // phase 1: top 12 bits (bins from score phase); re-zero bins
    for (int i = t; i < 4096; i += 1024) { sh[i] = __ldcg(&hb[i]); hb[i] = 0u; }
    __syncthreads();
    {
        unsigned s = sh[t * 4] + sh[t * 4 + 1] + sh[t * 4 + 2] + sh[t * 4 + 3];
        arr[t] = s;
        __syncthreads();
        for (int off = 1; off < 1024; off <<= 1) {
            unsigned v = (t + off < 1024) ? arr[t + off] : 0u;
            __syncthreads();
            arr[t] += v;
            __syncthreads();
        }
        unsigned above = arr[t] - s;
        if (above < (unsigned)k && above + s >= (unsigned)k) {
            unsigned cum = above;
            for (int j = 3; j >= 0; j--) {
                unsigned h = sh[t * 4 + j];
                if (cum + h >= (unsigned)k) { sPfx = t * 4 + j; sW = k - (int)cum; break; }
                cum += h;
            }
        }
    }
    __syncthreads();
    unsigned pfx1 = sPfx;
    int want = sW;

    // phase 2: bits [19:8]
    __syncthreads();
    for (int i = t; i < 4096; i += 1024) sh[i] = 0u;
    __syncthreads();
    for (int i = t; i < n; i += 1024) {
        unsigned kk = __ldcg(&kb[i]);
        if ((kk >> 20) == pfx1) atomicAdd(&sh[(kk >> 8) & 0xFFFu], 1u);
    }
    __syncthreads();
    {
        unsigned s = sh[t * 4] + sh[t * 4 + 1] + sh[t * 4 + 2] + sh[t * 4 + 3];
        arr[t] = s;
        __syncthreads();
        for (int off = 1; off < 1024; off <<= 1) {
            unsigned v = (t + off < 1024) ? arr[t + off] : 0u;
            __syncthreads();
            arr[t] += v;
            __syncthreads();
        }
        unsigned above = arr[t] - s;
        if (above < (unsigned)want && above + s >= (unsigned)want) {
            unsigned cum = above;
            for (int j = 3; j >= 0; j--) {
                unsigned h = sh[t * 4 + j];
                if (cum + h >= (unsigned)want) { sPfx = t * 4 + j; sW = want - (int)cum; break; }
                cum += h;
            }
        }
    }
    __syncthreads();
    unsigned pfx2 = sPfx;
    want = sW;
    unsigned pfx24 = (pfx1 << 12) | pfx2;

    // phase 3: final byte
    __syncthreads();
    if (t < 256) sh[t] = 0u;
    __syncthreads();
    for (int i = t; i < n; i += 1024) {
        unsigned kk = __ldcg(&kb[i]);
        if ((kk >> 8) == pfx24) atomicAdd(&sh[kk & 0xFFu], 1u);
    }
    __syncthreads();
    if (t == 0) {
        unsigned cum = 0;
        int d = 255;
        for (;;) {
            unsigned h = sh[d];
            if (cum + h >= (unsigned)want || d == 0) break;
            cum += h;
            d--;
        }
        thresh[g] = (pfx24 << 8) | (unsigned)d;
        allow[g] = want - (int)cum;
        cntK[g] = 0;
        cntE[g] = 0;
        if (g == 0) *eCn = 0;
        scnt[g] = 0u;                      // self-clean for next layer
    }
}

// fused compact + gather; reads g_dinv (never deg)
template <int FO>
__global__ void k_cg(const unsigned* __restrict__ key, const float* __restrict__ score,
                     const float* __restrict__ XB, const float* __restrict__ dinv,
                     const float* __restrict__ bias, int M, int n, int k,
                     const unsigned* __restrict__ thresh, const int* __restrict__ allow,
                     int* __restrict__ cntK, int* __restrict__ cntE,
                     int* __restrict__ remap, const float* __restrict__ pinv,
                     float* __restrict__ XA) {
    gdep();
    int lane = threadIdx.x & 31;
    int base = ((blockIdx.x * blockDim.x + threadIdx.x) >> 5) << 5;
    if (base >= M) return;
    int m = base + lane;
    bool active = (m < M);
    float pv = *pinv;

    int b = 0;
    bool keep = false;
    if (active) {
        b = m / n;
        unsigned kk = key[m], t = thresh[b];
        keep = kk > t;
        if (!keep && kk == t)
            keep = (atomicAdd(&cntE[b], 1) < allow[b]);
    }

    int nid = -1;
    bool uniformWarp = (base + 31 < M) && ((base / n) == ((base + 31) / n));
    if (uniformWarp) {
        unsigned keepmask = __ballot_sync(0xffffffffu, keep);
        int leader = __ffs(keepmask) - 1;
        int basepos = 0;
        if (keep && lane == leader)
            basepos = atomicAdd(&cntK[b], __popc(keepmask));
        basepos = __shfl_sync(0xffffffffu, basepos, (leader < 0) ? 0 : leader);
        if (keep)
            nid = b * k + basepos + __popc(keepmask & ((1u << lane) - 1u));
    } else {
        if (keep) nid = b * k + atomicAdd(&cntK[b], 1);
    }
    if (active) remap[m] = nid;

    float dvm = active ? dinv[m] : 0.f;
    float tv = keep ? tanhf(score[m] * pv) : 0.f;

    constexpr int LPR = FO / 4;
    constexpr int RPI = 32 / LPR;
    int sub = lane / LPR;
    int chunk = lane % LPR;
    float4 bv = *(const float4*)(bias + chunk * 4);

    unsigned fullkeep = __ballot_sync(0xffffffffu, keep);
    int count = __popc(fullkeep);
#pragma unroll 1
    for (int g = 0; g < count; g += RPI) {
        int slot = g + sub;
        int r = (slot < count) ? (int)__fns(fullkeep, 0, slot + 1) : 0;
        int nid_r = __shfl_sync(0xffffffffu, nid, r);
        float t_r  = __shfl_sync(0xffffffffu, tv, r);
        float dv_r = __shfl_sync(0xffffffffu, dvm, r);
        if (slot < count) {
            int m_r = base + r;
            float4 v = *(const float4*)(XB + (size_t)m_r * FO + chunk * 4);
            v.x = fmaxf(v.x * dv_r + bv.x, 0.f) * t_r;
            v.y = fmaxf(v.y * dv_r + bv.y, 0.f) * t_r;
            v.z = fmaxf(v.z * dv_r + bv.z, 0.f) * t_r;
            v.w = fmaxf(v.w * dv_r + bv.w, 0.f) * t_r;
            *(float4*)(XA + (size_t)nid_r * FO + chunk * 4) = v;
        }
    }
}

// edge remap/compact + next-layer degree (deg pre-zeroed by memset node)
__global__ void k_eremap(const int* __restrict__ srcO, const int* __restrict__ dstO,
                         const int* __restrict__ ecntO, const int* __restrict__ remap,
                         int* __restrict__ srcN, int* __restrict__ dstN,
                         int* __restrict__ ecntN, float* __restrict__ degN) {
    gdep();
    int E = *ecntO;
    int gt = blockIdx.x * blockDim.x + threadIdx.x;
    int lane = threadIdx.x & 31;
    int stride = gridDim.x * blockDim.x;
    for (int e = gt; __any_sync(0xffffffffu, e < E); e += stride) {
        bool in = (e < E);
        int s = -1, d = -1;
        if (in) {
            s = remap[srcO[e]];
            d = remap[dstO[e]];
        }
        bool valid = in && (s >= 0) && (d >= 0);
        unsigned mask = __ballot_sync(0xffffffffu, valid);
        if (!mask) continue;
        int leader = __ffs(mask) - 1;
        int basepos = 0;
        if (lane == leader) basepos = atomicAdd(ecntN, __popc(mask));
        basepos = __shfl_sync(0xffffffffu, basepos, leader);
        if (valid) {
            int pos = basepos + __popc(mask & ((1u << lane) - 1u));
            srcN[pos] = s;
            dstN[pos] = d;
            atomicAdd(&degN[d], 1.f);
        }
    }
}

// fused readout: 32 partial blocks; last block does the final reduce + MLP
__global__ void k_read12(const float* __restrict__ X, const float* __restrict__ meta,
                         const float* __restrict__ cw, const float* __restrict__ cb,
                         const float* __restrict__ fcw, const float* __restrict__ fcb,
                         const float* __restrict__ fc2w, const float* __restrict__ fc2b,
                         float* __restrict__ pmax, float* __restrict__ psum,
                         unsigned* __restrict__ ticket, float* __restrict__ out, int kn) {
    gdep();
    __shared__ float v[260];
    __shared__ float red[128];
    __shared__ unsigned sT;
    int b = blockIdx.x >> 3, s = blockIdx.x & 7, f = threadIdx.x;   // 128 threads
    int per = (kn + 7) / 8;
    int i0 = s * per, i1 = min(kn, i0 + per);
    float mx = -3.4e38f, sm = 0.f;
    const float* base = X + (size_t)b * kn * 128 + f;
    for (int i = i0; i < i1; i++) {
        float val = base[(size_t)i * 128];
        mx = fmaxf(mx, val);
        sm += val;
    }
    pmax[blockIdx.x * 128 + f] = mx;
    psum[blockIdx.x * 128 + f] = sm;

    __threadfence();
    __syncthreads();
    if (f == 0) sT = atomicAdd(ticket, 1u);
    __syncthreads();
    if (sT != 31u) return;
    __threadfence();
    if (f == 0) *ticket = 0u;              // self-clean

    for (int bb = 0; bb < BGR; bb++) {
        float mxf = -3.4e38f, smf = 0.f;
#pragma unroll
        for (int sl = 0; sl < 8; sl++) {
            mxf = fmaxf(mxf, __ldcg(&pmax[(bb * 8 + sl) * 128 + f]));
            smf += __ldcg(&psum[(bb * 8 + sl) * 128 + f]);
        }
        v[f] = mxf;
        v[128 + f] = smf / (float)kn;
        if (f < 4) {
            float mv = meta[bb] * cw[f] + cb[f];
            v[256 + f] = mv > 0.f ? mv : 0.f;
        }
        __syncthreads();
        float acc = fcb[f];
        for (int i = 0; i < 260; i++) acc += v[i] * fcw[i * 128 + f];
        float hv = acc > 0.f ? acc : 0.f;
        red[f] = hv * fc2w[f];
        __syncthreads();
        for (int ss = 64; ss > 0; ss >>= 1) {
            if (f < ss) red[f] += red[f + ss];
            __syncthreads();
        }
        if (f == 0) out[bb] = red[0] + fc2b[0];
        __syncthreads();
    }
}

// ---------------- host orchestration ----------------
static inline int gdiv(int n, int t) { return (n + t - 1) / t; }

template <typename Fn, typename... Args>
static inline void launch_pdl(Fn fn, int grid, int block, Args... args) {
    cudaLaunchConfig_t cfg = {};
    cfg.gridDim = dim3((unsigned)grid);
    cfg.blockDim = dim3((unsigned)block);
    cfg.dynamicSmemBytes = 0;
    cfg.stream = 0;
    cudaLaunchAttribute at[1];
    at[0].id = cudaLaunchAttributeProgrammaticStreamSerialization;
    at[0].val.programmaticStreamSerializationAllowed = 1;
    cfg.attrs = at;
    cfg.numAttrs = 1;
    cudaLaunchKernelEx(&cfg, fn, args...);
}

extern "C" void kernel_launch(void* const* d_in, const int* in_sizes, int n_in,
                              void* d_out, int out_size) {
    const float* x0   = (const float*)d_in[0];
    const int*   ei   = (const int*)  d_in[1];
    const float* meta = (const float*)d_in[2];
    const float* W[4]  = {(const float*)d_in[3], (const float*)d_in[6],
                          (const float*)d_in[9], (const float*)d_in[12]};
    const float* bb[4] = {(const float*)d_in[4], (const float*)d_in[7],
                          (const float*)d_in[10], (const float*)d_in[13]};
    const float* pp[4] = {(const float*)d_in[5], (const float*)d_in[8],
                          (const float*)d_in[11], (const float*)d_in[14]};
    const float* cw   = (const float*)d_in[15];
    const float* cb   = (const float*)d_in[16];
    const float* fcw  = (const float*)d_in[17];
    const float* fcb  = (const float*)d_in[18];
    const float* fc2w = (const float*)d_in[19];
    const float* fc2b = (const float*)d_in[20];
    float* out = (float*)d_out;

    float *H, *XB, *XA, *deg, *dinv, *score, *pinv, *pmax, *psum;
    unsigned *key, *thresh, *hist12, *misc;
    int *remap, *allow, *cntK, *cntE, *srcb, *dstb, *ecnt, *e0p;
    cudaGetSymbolAddress((void**)&H, g_H);
    cudaGetSymbolAddress((void**)&XB, g_XB);
    cudaGetSymbolAddress((void**)&XA, g_XA);
    cudaGetSymbolAddress((void**)&deg, g_deg);
    cudaGetSymbolAddress((void**)&dinv, g_dinv);
    cudaGetSymbolAddress((void**)&score, g_score);
    cudaGetSymbolAddress((void**)&key, g_key);
    cudaGetSymbolAddress((void**)&remap, g_remap);
    cudaGetSymbolAddress((void**)&srcb, g_srcbuf);
    cudaGetSymbolAddress((void**)&dstb, g_dstbuf);
    cudaGetSymbolAddress((void**)&ecnt, g_ecnt);
    cudaGetSymbolAddress((void**)&e0p, g_E0);
    cudaGetSymbolAddress((void**)&hist12, g_hist12);
    cudaGetSymbolAddress((void**)&thresh, g_thresh);
    cudaGetSymbolAddress((void**)&allow, g_allow);
    cudaGetSymbolAddress((void**)&cntK, g_cntK);
    cudaGetSymbolAddress((void**)&cntE, g_cntE);
    cudaGetSymbolAddress((void**)&pinv, g_pinv);
    cudaGetSymbolAddress((void**)&pmax, g_pmax);
    cudaGetSymbolAddress((void**)&psum, g_psum);
    cudaGetSymbolAddress((void**)&misc, g_misc);

    const int T = 256;

    // zero deg / hist / tickets via memset nodes, then fused deg0+pinv kernel
    cudaMemsetAsync(deg, 0, M0 * sizeof(float), 0);
    cudaMemsetAsync(hist12, 0, BGR * 4096 * sizeof(unsigned), 0);
    cudaMemsetAsync(misc, 0, 8 * sizeof(unsigned), 0);
    launch_pdl(k_init, gdiv(E0C, T), T, ei + E0C, pp[0], pp[1], pp[2], pp[3], deg, pinv);

    for (int i = 0; i < 4; i++) {
        int n = NIN[i], M = BGR * n, k = KK[i];
        const float* Xin = i ? XA : x0;
        const int* eS = i ? (srcb + ((i + 1) & 1) * E0C) : ei;
        const int* eD = i ? (dstb + ((i + 1) & 1) * E0C) : (ei + E0C);
        const int* eCuse = i ? (ecnt + ((i + 1) & 1)) : e0p;
        int* eSn = srcb + (i & 1) * E0C;
        int* eDn = dstb + (i & 1) * E0C;
        int* eCn = ecnt + (i & 1);

        // 1. H' = XB = (X@W)*dinv
        switch (i) {
            case 0: launch_pdl(k_mm<4, 32>,    gdiv(M, 32), T, Xin, W[0], deg, H, XB, M); break;
            case 1: launch_pdl(k_mm<32, 64>,   gdiv(M, 16), T, Xin, W[1], deg, H, XB, M); break;
            case 2: launch_pdl(k_mm<64, 128>,  gdiv(M, 8),  T, Xin, W[2], deg, H, XB, M); break;
            case 3: launch_pdl(k_mm<128, 128>, gdiv(M, 8),  T, Xin, W[3], deg, H, XB, M); break;
        }
        // 2. aggregate
        int aggGrid = (i == 0) ? gdiv(E0C * 8, T) : 4096;
        switch (i) {
            case 0: launch_pdl(k_agg<32>,  aggGrid, T, eS, eD, eCuse, H, XB); break;
            case 1: launch_pdl(k_agg<64>,  aggGrid, T, eS, eD, eCuse, H, XB); break;
            case 2: launch_pdl(k_agg<128>, aggGrid, T, eS, eD, eCuse, H, XB); break;
            case 3: launch_pdl(k_agg<128>, aggGrid, T, eS, eD, eCuse, H, XB); break;
        }
        // 3. fused score + select (last block per graph); stores dinv
        int bpg = gdiv(n, 32);
        switch (i) {
            case 0: launch_pdl(k_scoresel<32>,  BGR * bpg, 1024, XB, deg, bb[0], pp[0], n, bpg, k,
                               score, key, dinv, hist12, thresh, allow, cntK, cntE, eCn, misc); break;
            case 1: launch_pdl(k_scoresel<64>,  BGR * bpg, 1024, XB, deg, bb[1], pp[1], n, bpg, k,
                               score, key, dinv, hist12, thresh, allow, cntK, cntE, eCn, misc); break;
            case 2: launch_pdl(k_scoresel<128>, BGR * bpg, 1024, XB, deg, bb[2], pp[2], n, bpg, k,
                               score, key, dinv, hist12, thresh, allow, cntK, cntE, eCn, misc); break;
            case 3: launch_pdl(k_scoresel<128>, BGR * bpg, 1024, XB, deg, bb[3], pp[3], n, bpg, k,
                               score, key, dinv, hist12, thresh, allow, cntK, cntE, eCn, misc); break;
        }
        // 4. compact + gather (reads dinv, not deg)
        switch (i) {
            case 0: launch_pdl(k_cg<32>,  gdiv(M, T), T, key, score, XB, dinv, bb[0], M, n, k,
                               thresh, allow, cntK, cntE, remap, pinv + 0, XA); break;
            case 1: launch_pdl(k_cg<64>,  gdiv(M, T), T, key, score, XB, dinv, bb[1], M, n, k,
                               thresh, allow, cntK, cntE, remap, pinv + 1, XA); break;
            case 2: launch_pdl(k_cg<128>, gdiv(M, T), T, key, score, XB, dinv, bb[2], M, n, k,
                               thresh, allow, cntK, cntE, remap, pinv + 2, XA); break;
            case 3: launch_pdl(k_cg<128>, gdiv(M, T), T, key, score, XB, dinv, bb[3], M, n, k,
                               thresh, allow, cntK, cntE, remap, pinv + 3, XA); break;
        }
        // 5. zero next-layer deg (memset node) + edge remap
        if (i < 3) {
            cudaMemsetAsync(deg, 0, (size_t)BGR * k * sizeof(float), 0);
            int erGrid = (i == 0) ? gdiv(E0C, T) : 2048;
            launch_pdl(k_eremap, erGrid, T, eS, eD, eCuse, remap, eSn, eDn, eCn, deg);
        }
    }

    // fused readout
    launch_pdl(k_read12, BGR * 8, 128, XA, meta, cw, cb, fcw, fcb, fc2w, fc2b,
               pmax, psum, misc + 4, out, KK[3]);
    (void)in_sizes; (void)n_in; (void)out_size;
}